// round 3
// baseline (speedup 1.0000x reference)
#include <cuda_runtime.h>
#include <math.h>

#define Nn 50000
#define Cc 64
#define Ee 800000
#define NC (Nn*Cc)

// ---------------- device scratch (no allocations allowed) ----------------
__device__ float d_s[4][NC];        // states 2..5
__device__ float d_P[NC];           // combined GCN input per step
__device__ float d_hw[5][NC];       // GAT hw_j per step
__device__ float d_agg[4][NC];      // SAGE mean aggregates of states {x, s2, s3, s4}
__device__ float d_asrc[5][Nn];
__device__ float d_adst[5][Nn];
__device__ int   d_indeg[Nn];
__device__ int   d_rowptr[Nn+1];
__device__ int   d_fill[Nn];
__device__ int   d_csrc[Ee];
__device__ float d_dinv[Nn];        // rsqrt(indeg+1)  (GCN, self-looped degree)
__device__ float d_cntinv[Nn];      // 1/max(indeg,1)  (SAGE mean)
__device__ float d_w[14][5];        // softmax(alphas)
__device__ float d_bias[4][Cc];     // per-step combined bias

// ---------------- zero indeg (no memset nodes on __device__ symbols) ----
__global__ void zero_indeg_kernel()
{
    int i = blockIdx.x*blockDim.x + threadIdx.x;
    if (i < Nn) d_indeg[i] = 0;
}

// ---------------- prep: mixture weights + combined biases ----------------
__global__ void prep_w_kernel(const float* alphas, const float* gcn_b,
                              const float* sage_b, const float* gat_b)
{
    int t = threadIdx.x;
    if (t < 14) {
        float v[5]; float m = -1e30f;
        for (int i = 0; i < 5; i++) { v[i] = alphas[t*5+i]; m = fmaxf(m, v[i]); }
        float s = 0.f;
        for (int i = 0; i < 5; i++) { v[i] = expf(v[i]-m); s += v[i]; }
        for (int i = 0; i < 5; i++) d_w[t][i] = v[i]/s;
    }
    __syncthreads();
    int step = t >> 6, c = t & 63;   // 256 threads -> 4 steps x 64 channels
    const int koff[4] = {0,2,5,9};
    float b = 0.f;
    for (int j = 0; j < step+2; j++) {
        int k = koff[step] + j;
        b += d_w[k][0]*gcn_b[k*Cc+c] + d_w[k][1]*sage_b[k*Cc+c] + d_w[k][2]*gat_b[k*Cc+c];
    }
    d_bias[step][c] = b;
}

// ---------------- CSR construction (edge_index is int32: JAX x64 disabled) ----
__global__ void degree_kernel(const int* ei)
{
    int e = blockIdx.x*blockDim.x + threadIdx.x;
    if (e < Ee) {
        int d = ei[Ee + e];
        if ((unsigned)d < (unsigned)Nn) atomicAdd(&d_indeg[d], 1);
    }
}

__global__ void scan_kernel()
{
    __shared__ int sh[1024];
    __shared__ int carry;
    int t = threadIdx.x;
    if (t == 0) carry = 0;
    __syncthreads();
    for (int base = 0; base < Nn; base += 1024) {
        int i = base + t;
        int v = (i < Nn) ? d_indeg[i] : 0;
        sh[t] = v;
        __syncthreads();
        for (int off = 1; off < 1024; off <<= 1) {
            int xv = (t >= off) ? sh[t-off] : 0;
            __syncthreads();
            sh[t] += xv;
            __syncthreads();
        }
        int excl = sh[t] - v;
        if (i < Nn) {
            int r = carry + excl;
            d_rowptr[i] = r;
            d_fill[i]   = r;
            d_dinv[i]   = rsqrtf((float)(v+1));
            d_cntinv[i] = 1.0f / (float)(v > 0 ? v : 1);
        }
        __syncthreads();
        if (t == 0) carry += sh[1023];
        __syncthreads();
    }
    if (t == 0) d_rowptr[Nn] = carry;
}

__global__ void fill_kernel(const int* ei)
{
    int e = blockIdx.x*blockDim.x + threadIdx.x;
    if (e < Ee) {
        int s = ei[e];
        int d = ei[Ee + e];
        if ((unsigned)s < (unsigned)Nn && (unsigned)d < (unsigned)Nn) {
            int pos = atomicAdd(&d_fill[d], 1);
            if ((unsigned)pos < (unsigned)Ee) d_csrc[pos] = s;
        }
    }
}

// ---------------- multi-job GEMM: D = sum_t scale_t * A_t(50000x64) @ W_t(64x64) ----------------
struct GTerm { const float* A; const float* W; int wk; int wcol; };
struct GJob  { float* D; int nt; GTerm t[10]; };
struct GArgs { GJob job[7]; };

__global__ void gemm_kernel(GArgs args)
{
    extern __shared__ float sm[];
    float* Ast = sm;             // [64][132]  A transposed (k-major), padded
    float* Ws  = sm + 64*132;    // [64][64]
    const GJob& J = args.job[blockIdx.y];
    int tid = threadIdx.x;
    int tx = tid & 15, ty = tid >> 4;     // 16 row-groups x 8 col-groups
    int row0 = blockIdx.x * 128;
    float acc[8][8];
    #pragma unroll
    for (int m = 0; m < 8; m++)
        #pragma unroll
        for (int n = 0; n < 8; n++) acc[m][n] = 0.f;

    for (int tm = 0; tm < J.nt; tm++) {
        const float* A = J.t[tm].A;
        const float* W = J.t[tm].W;
        float sc = (J.t[tm].wk >= 0) ? d_w[J.t[tm].wk][J.t[tm].wcol] : 1.0f;
        __syncthreads();
        // load A tile transposed into smem
        #pragma unroll
        for (int it = 0; it < 16; it++) {
            int idx = tid + it*128;           // 0..2047
            int r = idx >> 4, k4 = (idx & 15) * 4;
            float4 v = make_float4(0.f,0.f,0.f,0.f);
            int gr = row0 + r;
            if (gr < Nn) v = *(const float4*)(A + (size_t)gr*Cc + k4);
            Ast[(k4+0)*132 + r] = v.x;
            Ast[(k4+1)*132 + r] = v.y;
            Ast[(k4+2)*132 + r] = v.z;
            Ast[(k4+3)*132 + r] = v.w;
        }
        // load W pre-scaled
        #pragma unroll
        for (int it = 0; it < 8; it++) {
            int idx = tid + it*128;           // 0..1023 float4s
            float4 v = *(const float4*)(W + idx*4);
            Ws[idx*4+0] = sc*v.x; Ws[idx*4+1] = sc*v.y;
            Ws[idx*4+2] = sc*v.z; Ws[idx*4+3] = sc*v.w;
        }
        __syncthreads();
        #pragma unroll 8
        for (int k = 0; k < 64; k++) {
            float4 a0 = *(const float4*)(Ast + k*132 + tx*8);
            float4 a1 = *(const float4*)(Ast + k*132 + tx*8 + 4);
            float4 b0 = *(const float4*)(Ws + k*64 + ty*8);
            float4 b1 = *(const float4*)(Ws + k*64 + ty*8 + 4);
            float a[8] = {a0.x,a0.y,a0.z,a0.w,a1.x,a1.y,a1.z,a1.w};
            float b[8] = {b0.x,b0.y,b0.z,b0.w,b1.x,b1.y,b1.z,b1.w};
            #pragma unroll
            for (int m = 0; m < 8; m++)
                #pragma unroll
                for (int n = 0; n < 8; n++)
                    acc[m][n] += a[m]*b[n];
        }
    }
    #pragma unroll
    for (int m = 0; m < 8; m++) {
        int gr = row0 + tx*8 + m;
        if (gr < Nn) {
            float* Dp = J.D + (size_t)gr*Cc + ty*8;
            *(float4*)Dp     = make_float4(acc[m][0],acc[m][1],acc[m][2],acc[m][3]);
            *(float4*)(Dp+4) = make_float4(acc[m][4],acc[m][5],acc[m][6],acc[m][7]);
        }
    }
}

// ---------------- GAT attention scalars: asrc/adst per node per j ----------------
__global__ void rowdot_kernel(const float* ga_src, const float* ga_dst, int ko)
{
    int j = blockIdx.y;
    int k = ko + j;
    int gw = (blockIdx.x*blockDim.x + threadIdx.x) >> 5;
    if (gw >= Nn) return;
    int lane = threadIdx.x & 31;
    float2 h  = *(const float2*)(d_hw[j] + (size_t)gw*Cc + 2*lane);
    float2 as = *(const float2*)(ga_src + k*Cc + 2*lane);
    float2 ad = *(const float2*)(ga_dst + k*Cc + 2*lane);
    float s1 = h.x*as.x + h.y*as.y;
    float s2 = h.x*ad.x + h.y*ad.y;
    #pragma unroll
    for (int off = 16; off > 0; off >>= 1) {
        s1 += __shfl_xor_sync(0xffffffffu, s1, off);
        s2 += __shfl_xor_sync(0xffffffffu, s2, off);
    }
    if (lane == 0) { d_asrc[j][gw] = s1; d_adst[j][gw] = s2; }
}

// ---------------- SAGE mean aggregate (no self loops) ----------------
__global__ void sage_agg_kernel(float* agg, const float* h)
{
    int gw = (blockIdx.x*blockDim.x + threadIdx.x) >> 5;
    if (gw >= Nn) return;
    int lane = threadIdx.x & 31;
    int v = gw;
    int beg = d_rowptr[v], end = d_rowptr[v+1];
    float2 acc = make_float2(0.f,0.f);
    for (int e0 = beg; e0 < end; e0 += 32) {
        int idx = e0 + lane;
        int s = 0;
        if (idx < end) s = d_csrc[idx];
        int cnt = min(32, end - e0);
        for (int t2 = 0; t2 < cnt; t2++) {
            int ss = __shfl_sync(0xffffffffu, s, t2);
            float2 p = *(const float2*)(h + (size_t)ss*Cc + 2*lane);
            acc.x += p.x; acc.y += p.y;
        }
    }
    float ci = d_cntinv[v];
    *(float2*)(agg + (size_t)v*Cc + 2*lane) = make_float2(acc.x*ci, acc.y*ci);
}

// ---------------- GCN aggregate over combined P (self loops included) ----------------
__global__ void gcn_agg_kernel(float* S)
{
    int gw = (blockIdx.x*blockDim.x + threadIdx.x) >> 5;
    if (gw >= Nn) return;
    int lane = threadIdx.x & 31;
    int v = gw;
    int beg = d_rowptr[v], end = d_rowptr[v+1];
    float2 acc = make_float2(0.f,0.f);
    for (int e0 = beg; e0 < end; e0 += 32) {
        int idx = e0 + lane;
        int s = 0; float cf = 0.f;
        if (idx < end) { s = d_csrc[idx]; cf = d_dinv[s]; }
        int cnt = min(32, end - e0);
        for (int t2 = 0; t2 < cnt; t2++) {
            int ss = __shfl_sync(0xffffffffu, s, t2);
            float cc = __shfl_sync(0xffffffffu, cf, t2);
            float2 p = *(const float2*)(d_P + (size_t)ss*Cc + 2*lane);
            acc.x += cc*p.x; acc.y += cc*p.y;
        }
    }
    float dv = d_dinv[v];
    float2 pv = *(const float2*)(d_P + (size_t)v*Cc + 2*lane);
    float2 sv = *(float2*)(S + (size_t)v*Cc + 2*lane);
    sv.x += dv*acc.x + dv*dv*pv.x;
    sv.y += dv*acc.y + dv*dv*pv.y;
    *(float2*)(S + (size_t)v*Cc + 2*lane) = sv;
}

// ---------------- identity branch + combined bias ----------------
struct PWArgs { const float* st[5]; };
__global__ void pointwise_kernel(float* S, PWArgs a, int ko, int nj, int step)
{
    int idx = blockIdx.x*blockDim.x + threadIdx.x;
    if (idx >= NC) return;
    int c = idx & 63;
    float v = d_bias[step][c];
    for (int j = 0; j < nj; j++)
        v += d_w[ko+j][3] * a.st[j][idx];
    S[idx] += v;
}

// ---------------- GAT: per-node segment softmax + weighted gather, all j ----------------
__global__ void gat_agg_kernel(float* S, int ko, int nj)
{
    int gw = (blockIdx.x*blockDim.x + threadIdx.x) >> 5;
    if (gw >= Nn) return;
    int lane = threadIdx.x & 31;
    int v = gw;
    int beg = d_rowptr[v], end = d_rowptr[v+1];
    float2 tot = make_float2(0.f,0.f);
    for (int j = 0; j < nj; j++) {
        const float* hw = d_hw[j];
        const float* as = d_asrc[j];
        float adv = d_adst[j][v];
        float e0s = as[v] + adv;
        float eself = e0s > 0.f ? e0s : 0.2f*e0s;
        // pass 1: max
        float m = eself;
        for (int e0 = beg; e0 < end; e0 += 32) {
            int idx = e0 + lane;
            float e = -1e30f;
            if (idx < end) {
                float tv = as[d_csrc[idx]] + adv;
                e = tv > 0.f ? tv : 0.2f*tv;
            }
            m = fmaxf(m, e);
        }
        #pragma unroll
        for (int off = 16; off > 0; off >>= 1)
            m = fmaxf(m, __shfl_xor_sync(0xffffffffu, m, off));
        // pass 2: exp-sum + weighted feature gather
        float denom = 0.f;
        float2 acc = make_float2(0.f,0.f);
        {
            float p = __expf(eself - m);
            if (lane == 0) denom = p;
            float2 hv = *(const float2*)(hw + (size_t)v*Cc + 2*lane);
            acc.x += p*hv.x; acc.y += p*hv.y;
        }
        for (int e0 = beg; e0 < end; e0 += 32) {
            int idx = e0 + lane;
            int s = 0; float p = 0.f;
            if (idx < end) {
                s = d_csrc[idx];
                float tv = as[s] + adv;
                tv = tv > 0.f ? tv : 0.2f*tv;
                p = __expf(tv - m);
            }
            denom += p;
            int cnt = min(32, end - e0);
            for (int t2 = 0; t2 < cnt; t2++) {
                float pp = __shfl_sync(0xffffffffu, p, t2);
                int ss = __shfl_sync(0xffffffffu, s, t2);
                float2 hsv = *(const float2*)(hw + (size_t)ss*Cc + 2*lane);
                acc.x += pp*hsv.x; acc.y += pp*hsv.y;
            }
        }
        #pragma unroll
        for (int off = 16; off > 0; off >>= 1)
            denom += __shfl_xor_sync(0xffffffffu, denom, off);
        float wcoef = d_w[ko+j][2] / denom;
        tot.x += wcoef*acc.x; tot.y += wcoef*acc.y;
    }
    float2 sv = *(float2*)(S + (size_t)v*Cc + 2*lane);
    sv.x += tot.x; sv.y += tot.y;
    *(float2*)(S + (size_t)v*Cc + 2*lane) = sv;
}

// ---------------- output: mean of states[2..5] ----------------
__global__ void final_kernel(float* out)
{
    int idx = blockIdx.x*blockDim.x + threadIdx.x;
    if (idx >= NC) return;
    out[idx] = 0.25f*(d_s[0][idx] + d_s[1][idx] + d_s[2][idx] + d_s[3][idx]);
}

// ---------------- host orchestration ----------------
extern "C" void kernel_launch(void* const* d_in, const int* in_sizes, int n_in,
                              void* d_out, int out_size)
{
    const float* x       = (const float*)d_in[0];
    const int*   ei      = (const int*)d_in[1];     // int32! (JAX x64 disabled)
    const float* alphas  = (const float*)d_in[2];
    const float* gcn_W   = (const float*)d_in[3];
    const float* gcn_b   = (const float*)d_in[4];
    const float* sage_Wl = (const float*)d_in[5];
    const float* sage_Wr = (const float*)d_in[6];
    const float* sage_b  = (const float*)d_in[7];
    const float* gat_W   = (const float*)d_in[8];
    const float* ga_src  = (const float*)d_in[9];
    const float* ga_dst  = (const float*)d_in[10];
    const float* gat_b   = (const float*)d_in[11];
    float* out = (float*)d_out;
    (void)in_sizes; (void)n_in; (void)out_size;

    float *sbase, *Pp, *hwbase, *aggbase;
    cudaGetSymbolAddress((void**)&sbase,   d_s);
    cudaGetSymbolAddress((void**)&Pp,      d_P);
    cudaGetSymbolAddress((void**)&hwbase,  d_hw);
    cudaGetSymbolAddress((void**)&aggbase, d_agg);

    const int SMEMSZ = (64*132 + 64*64) * 4;   // 50176 B
    cudaFuncSetAttribute(gemm_kernel, cudaFuncAttributeMaxDynamicSharedMemorySize, SMEMSZ);

    // ---- prep ----
    zero_indeg_kernel<<<(Nn+511)/512,512>>>();
    prep_w_kernel<<<1,256>>>(alphas, gcn_b, sage_b, gat_b);
    degree_kernel<<<(Ee+255)/256,256>>>(ei);
    scan_kernel<<<1,1024>>>();
    fill_kernel<<<(Ee+255)/256,256>>>(ei);
    sage_agg_kernel<<<6250,256>>>(aggbase, x);          // agg of x (states 0 and 1)

    const int koff[4] = {0,2,5,9};
    for (int step = 0; step < 4; step++) {
        int nj = step + 2;
        int ko = koff[step];
        if (step >= 1)   // aggregate of newest state: d_agg[step] = mean-agg(states[step+1])
            sage_agg_kernel<<<6250,256>>>(aggbase + (size_t)step*NC,
                                          sbase + (size_t)(step-1)*NC);

        GArgs ga;
        // job0: combined GCN input P
        ga.job[0].D = Pp; ga.job[0].nt = nj;
        for (int j = 0; j < nj; j++) {
            const float* st = (j <= 1) ? x : sbase + (size_t)(j-2)*NC;
            ga.job[0].t[j] = GTerm{ st, gcn_W + (size_t)(ko+j)*4096, ko+j, 0 };
        }
        // job1: S (new state) = sum of SAGE terms (first writer of S)
        ga.job[1].D = sbase + (size_t)step*NC; ga.job[1].nt = 2*nj;
        for (int j = 0; j < nj; j++) {
            const float* st = (j <= 1) ? x : sbase + (size_t)(j-2)*NC;
            const float* ag = (j <= 1) ? aggbase : aggbase + (size_t)(j-1)*NC;
            ga.job[1].t[2*j]   = GTerm{ ag, sage_Wl + (size_t)(ko+j)*4096, ko+j, 1 };
            ga.job[1].t[2*j+1] = GTerm{ st, sage_Wr + (size_t)(ko+j)*4096, ko+j, 1 };
        }
        // jobs 2..: GAT hw_j (unscaled — attention is nonlinear in hw)
        for (int j = 0; j < nj; j++) {
            const float* st = (j <= 1) ? x : sbase + (size_t)(j-2)*NC;
            ga.job[2+j].D = hwbase + (size_t)j*NC; ga.job[2+j].nt = 1;
            ga.job[2+j].t[0] = GTerm{ st, gat_W + (size_t)(ko+j)*4096, -1, 0 };
        }
        gemm_kernel<<<dim3(391, 2+nj), 128, SMEMSZ>>>(ga);

        rowdot_kernel<<<dim3(6250, nj), 256>>>(ga_src, ga_dst, ko);
        gcn_agg_kernel<<<6250,256>>>(sbase + (size_t)step*NC);

        PWArgs pw;
        for (int j = 0; j < nj; j++)
            pw.st[j] = (j <= 1) ? x : sbase + (size_t)(j-2)*NC;
        pointwise_kernel<<<6250,512>>>(sbase + (size_t)step*NC, pw, ko, nj, step);

        gat_agg_kernel<<<6250,256>>>(sbase + (size_t)step*NC, ko, nj);
    }
    final_kernel<<<6250,512>>>(out);
}